// round 3
// baseline (speedup 1.0000x reference)
#include <cuda_runtime.h>
#include <float.h>
#include <math.h>

// x = [B=16, C=2048, H=48, W=64] fp32. 21 regions, 6 row ranges from
// 6 row segments (breakpoints 0,12,16,24,32,36,48 -- multiples of 4).
#define B_  16
#define C_  2048
#define H_  48
#define W_  64
#define NPLANE (B_ * C_)
#define R_  21
#define EPS_ 1e-6f

__device__ float g_vecs[B_ * R_ * C_];    // [b][r][c]

// RR0=[0,48) RR1=[0,32) RR2=[16,48) RR3=[0,24) RR4=[12,36) RR5=[24,48)
__constant__ int REG_RR[R_] = {
    0,
    0, 0,
    1, 1, 1,
    2, 2, 2,
    3, 3, 3, 3,
    4, 4, 4, 4,
    5, 5, 5, 5
};
__constant__ int REG_C0[R_] = {
    0,
    0, 16,
    0, 16, 32,
    0, 16, 32,
    0, 13, 26, 40,
    0, 13, 26, 40,
    0, 13, 26, 40
};
__constant__ int REG_C1[R_] = {
    64,
    48, 64,
    32, 48, 64,
    32, 48, 64,
    24, 37, 50, 64,
    24, 37, 50, 64,
    24, 37, 50, 64
};

__device__ __forceinline__ float4 fmax4(float4 a, float4 b) {
    return make_float4(fmaxf(a.x, b.x), fmaxf(a.y, b.y),
                       fmaxf(a.z, b.z), fmaxf(a.w, b.w));
}

// ---------------------------------------------------------------------------
// Kernel 1: one block per (b,c) plane, 64 threads.
// Thread t: quad q=t&15 (cols 4q..4q+3), row phase r0=t>>4; rows r0+4k,
// k=0..11 -> 12 front-batched LDG.128 (immediate offsets from one base).
// Segment of row r0+4k depends only on k:
//   k 0-2 -> seg0 [0,12); k=3 -> seg1; k 4-5 -> seg2; k 6-7 -> seg3;
//   k=8 -> seg4; k 9-11 -> seg5.
// No shuffles: per-phase segment maxes go to smem; per-column pass combines.
// ---------------------------------------------------------------------------
__global__ __launch_bounds__(64) void rpool_max_kernel(
    const float* __restrict__ x, float* __restrict__ vecs)
{
    const int plane = blockIdx.x;             // b * C + c
    const int t = threadIdx.x;
    const int q = t & 15;
    const int r0 = t >> 4;                    // 0..3
    const float4* __restrict__ p4 =
        reinterpret_cast<const float4*>(x + (size_t)plane * (H_ * W_))
        + r0 * 16 + q;                        // 4-row stride = 64 float4

    // Front-batch all 12 wide loads for MLP.
    const float4 v0  = p4[0];
    const float4 v1  = p4[64];
    const float4 v2  = p4[128];
    const float4 v3  = p4[192];
    const float4 v4  = p4[256];
    const float4 v5  = p4[320];
    const float4 v6  = p4[384];
    const float4 v7  = p4[448];
    const float4 v8  = p4[512];
    const float4 v9  = p4[576];
    const float4 v10 = p4[640];
    const float4 v11 = p4[704];

    const float4 s0 = fmax4(fmax4(v0, v1), v2);   // rows [0,12)
    const float4 s1 = v3;                          // [12,16)
    const float4 s2 = fmax4(v4, v5);               // [16,24)
    const float4 s3 = fmax4(v6, v7);               // [24,32)
    const float4 s4 = v8;                          // [32,36)
    const float4 s5 = fmax4(fmax4(v9, v10), v11);  // [36,48)

    __shared__ float segs[4][6][W_];   // [phase][seg][col], 6 KB
    reinterpret_cast<float4*>(segs[r0][0])[q] = s0;
    reinterpret_cast<float4*>(segs[r0][1])[q] = s1;
    reinterpret_cast<float4*>(segs[r0][2])[q] = s2;
    reinterpret_cast<float4*>(segs[r0][3])[q] = s3;
    reinterpret_cast<float4*>(segs[r0][4])[q] = s4;
    reinterpret_cast<float4*>(segs[r0][5])[q] = s5;
    __syncthreads();

    // Per-column: fold 4 phases, build 6 row-range maxes (in registers).
    const int col = t;
    const float c0 = fmaxf(fmaxf(segs[0][0][col], segs[1][0][col]),
                           fmaxf(segs[2][0][col], segs[3][0][col]));
    const float c1 = fmaxf(fmaxf(segs[0][1][col], segs[1][1][col]),
                           fmaxf(segs[2][1][col], segs[3][1][col]));
    const float c2 = fmaxf(fmaxf(segs[0][2][col], segs[1][2][col]),
                           fmaxf(segs[2][2][col], segs[3][2][col]));
    const float c3 = fmaxf(fmaxf(segs[0][3][col], segs[1][3][col]),
                           fmaxf(segs[2][3][col], segs[3][3][col]));
    const float c4 = fmaxf(fmaxf(segs[0][4][col], segs[1][4][col]),
                           fmaxf(segs[2][4][col], segs[3][4][col]));
    const float c5 = fmaxf(fmaxf(segs[0][5][col], segs[1][5][col]),
                           fmaxf(segs[2][5][col], segs[3][5][col]));
    const float m012 = fmaxf(fmaxf(c0, c1), c2);
    const float m345 = fmaxf(fmaxf(c3, c4), c5);

    __syncthreads();   // all reads of segs done; reuse it as rr[6][64]
    float (*rr)[W_] = segs[0];
    rr[0][col] = fmaxf(m012, m345);                    // [0,48)
    rr[1][col] = fmaxf(m012, c3);                      // [0,32)
    rr[2][col] = fmaxf(fmaxf(c2, c3), fmaxf(c4, c5));  // [16,48)
    rr[3][col] = m012;                                 // [0,24)
    rr[4][col] = fmaxf(fmaxf(c1, c2), fmaxf(c3, c4));  // [12,36)
    rr[5][col] = m345;                                 // [24,48)
    __syncthreads();

    const int warp = t >> 5, lane = t & 31;
    const int b = plane >> 11;          // / C_
    const int c = plane & (C_ - 1);     // % C_

    for (int reg = warp; reg < R_; reg += 2) {
        const int ri = REG_RR[reg];
        const int cc0 = REG_C0[reg];
        const int cc1 = REG_C1[reg];
        float m = -FLT_MAX;
        for (int cc = cc0 + lane; cc < cc1; cc += 32)
            m = fmaxf(m, rr[ri][cc]);
        #pragma unroll
        for (int o = 16; o > 0; o >>= 1)
            m = fmaxf(m, __shfl_xor_sync(0xffffffffu, m, o));
        if (lane == 0)
            vecs[((size_t)(b * R_ + reg)) * C_ + c] = m;
    }
}

// ---------------------------------------------------------------------------
// Kernel 2 (fused norm + aggregate): one block per batch b, 256 threads.
// Pass 1: 21 per-region L2 norms (float4 loads, 21 scalar accumulators,
//         outer loop NOT unrolled to cap register pressure).
// Pass 2: weighted region sum + global L2 normalize, float4 in/out.
// vecs (2.75 MB) is L2-resident.
// ---------------------------------------------------------------------------
__global__ __launch_bounds__(256) void rpool_normagg_kernel(
    const float* __restrict__ vecs, float* __restrict__ out)
{
    const int b = blockIdx.x;
    const int tid = threadIdx.x;
    const int lane = tid & 31, warp = tid >> 5;
    const float4* __restrict__ vb4 =
        reinterpret_cast<const float4*>(vecs + (size_t)b * R_ * C_);
    // per region: C_/4 = 512 float4

    // ---- pass 1: per-region sum of squares ----
    float acc[R_];
    #pragma unroll
    for (int r = 0; r < R_; r++) acc[r] = 0.f;

    #pragma unroll 1
    for (int i = 0; i < 2; i++) {
        const int f = tid + i * 256;
        float4 v[R_];
        #pragma unroll
        for (int r = 0; r < R_; r++) v[r] = vb4[r * 512 + f];
        #pragma unroll
        for (int r = 0; r < R_; r++)
            acc[r] += v[r].x * v[r].x + v[r].y * v[r].y
                    + v[r].z * v[r].z + v[r].w * v[r].w;
    }
    #pragma unroll
    for (int r = 0; r < R_; r++) {
        #pragma unroll
        for (int o = 16; o > 0; o >>= 1)
            acc[r] += __shfl_xor_sync(0xffffffffu, acc[r], o);
    }
    __shared__ float ws[8][R_];
    if (lane == 0) {
        #pragma unroll
        for (int r = 0; r < R_; r++) ws[warp][r] = acc[r];
    }
    __syncthreads();
    __shared__ float inv[R_];
    if (tid < R_) {
        float s = 0.f;
        #pragma unroll
        for (int w = 0; w < 8; w++) s += ws[w][tid];
        inv[tid] = 1.0f / (sqrtf(s) + EPS_);
    }
    __syncthreads();

    // ---- pass 2: aggregate + global L2 normalize ----
    float4 sv[2];
    float local = 0.f;
    #pragma unroll 1
    for (int i = 0; i < 2; i++) {
        const int f = tid + i * 256;
        float4 s = make_float4(0.f, 0.f, 0.f, 0.f);
        #pragma unroll
        for (int r = 0; r < R_; r++) {
            const float4 v = vb4[r * 512 + f];
            const float w = inv[r];
            s.x += v.x * w; s.y += v.y * w;
            s.z += v.z * w; s.w += v.w * w;
        }
        sv[i] = s;
        local += s.x * s.x + s.y * s.y + s.z * s.z + s.w * s.w;
    }

    #pragma unroll
    for (int o = 16; o > 0; o >>= 1)
        local += __shfl_xor_sync(0xffffffffu, local, o);
    __shared__ float wsum[8];
    if (lane == 0) wsum[warp] = local;
    __syncthreads();
    __shared__ float s_invnorm;
    if (warp == 0) {
        float v = (lane < 8) ? wsum[lane] : 0.f;
        #pragma unroll
        for (int o = 4; o > 0; o >>= 1)
            v += __shfl_xor_sync(0xffffffffu, v, o);
        if (lane == 0) s_invnorm = 1.0f / (sqrtf(v) + EPS_);
    }
    __syncthreads();

    const float invn = s_invnorm;
    float4* __restrict__ out4 = reinterpret_cast<float4*>(out) + (size_t)b * 512;
    #pragma unroll
    for (int i = 0; i < 2; i++) {
        const int f = tid + i * 256;
        float4 s = sv[i];
        s.x *= invn; s.y *= invn; s.z *= invn; s.w *= invn;
        out4[f] = s;
    }
}

extern "C" void kernel_launch(void* const* d_in, const int* in_sizes, int n_in,
                              void* d_out, int out_size)
{
    const float* x = (const float*)d_in[0];
    float* out = (float*)d_out;

    float* vecs;
    cudaGetSymbolAddress((void**)&vecs, g_vecs);

    rpool_max_kernel<<<NPLANE, 64>>>(x, vecs);
    rpool_normagg_kernel<<<B_, 256>>>(vecs, out);
}

// round 4
// speedup vs baseline: 1.1536x; 1.1536x over previous
#include <cuda_runtime.h>
#include <float.h>
#include <math.h>

// x = [B=16, C=2048, H=48, W=64] fp32. 21 regions; 6 row ranges from 6 row
// segments (breakpoints 0,12,16,24,32,36,48).
#define B_  16
#define C_  2048
#define H_  48
#define W_  64
#define NPLANE (B_ * C_)
#define R_  21
#define EPS_ 1e-6f

__device__ float g_vecs[B_ * R_ * C_];    // [b][r][c]
__device__ float g_inv[B_ * R_];          // 1/(||v||+eps) per (b,r)

// RR0=[0,48) RR1=[0,32) RR2=[16,48) RR3=[0,24) RR4=[12,36) RR5=[24,48)
__constant__ int REG_RR[R_] = {
    0,
    0, 0,
    1, 1, 1,
    2, 2, 2,
    3, 3, 3, 3,
    4, 4, 4, 4,
    5, 5, 5, 5
};
__constant__ int REG_C0[R_] = {
    0,
    0, 16,
    0, 16, 32,
    0, 16, 32,
    0, 13, 26, 40,
    0, 13, 26, 40,
    0, 13, 26, 40
};
__constant__ int REG_C1[R_] = {
    64,
    48, 64,
    32, 48, 64,
    32, 48, 64,
    24, 37, 50, 64,
    24, 37, 50, 64,
    24, 37, 50, 64
};

// ---------------------------------------------------------------------------
// Kernel 1 (R1-proven): one block per (b,c) plane, 64 threads = one per
// column. Scalar column-walk: warp-coalesced LDG.32 (1 L1tex wavefront per
// load, cross-LDG rate). 6 row-segment maxes in registers, 6 row-range maxes
// in smem, 21 region column reductions via shuffles.
// ---------------------------------------------------------------------------
__global__ __launch_bounds__(64) void rpool_max_kernel(
    const float* __restrict__ x, float* __restrict__ vecs)
{
    const int plane = blockIdx.x;             // b * C + c
    const float* __restrict__ p = x + (size_t)plane * (H_ * W_);
    const int col = threadIdx.x;              // 0..63

    float s0 = -FLT_MAX, s1 = -FLT_MAX, s2 = -FLT_MAX;
    float s3 = -FLT_MAX, s4 = -FLT_MAX, s5 = -FLT_MAX;

    #pragma unroll
    for (int r = 0; r < 12; r++)  s0 = fmaxf(s0, p[r * W_ + col]);
    #pragma unroll
    for (int r = 12; r < 16; r++) s1 = fmaxf(s1, p[r * W_ + col]);
    #pragma unroll
    for (int r = 16; r < 24; r++) s2 = fmaxf(s2, p[r * W_ + col]);
    #pragma unroll
    for (int r = 24; r < 32; r++) s3 = fmaxf(s3, p[r * W_ + col]);
    #pragma unroll
    for (int r = 32; r < 36; r++) s4 = fmaxf(s4, p[r * W_ + col]);
    #pragma unroll
    for (int r = 36; r < 48; r++) s5 = fmaxf(s5, p[r * W_ + col]);

    __shared__ float rr[6][W_];
    const float m012 = fmaxf(fmaxf(s0, s1), s2);
    const float m345 = fmaxf(fmaxf(s3, s4), s5);
    rr[0][col] = fmaxf(m012, m345);                     // rows [0,48)
    rr[1][col] = fmaxf(m012, s3);                       // rows [0,32)
    rr[2][col] = fmaxf(fmaxf(s2, s3), fmaxf(s4, s5));   // rows [16,48)
    rr[3][col] = m012;                                  // rows [0,24)
    rr[4][col] = fmaxf(fmaxf(s1, s2), fmaxf(s3, s4));   // rows [12,36)
    rr[5][col] = m345;                                  // rows [24,48)
    __syncthreads();

    const int warp = threadIdx.x >> 5;
    const int lane = threadIdx.x & 31;
    const int b = plane >> 11;          // / C_
    const int c = plane & (C_ - 1);     // % C_

    for (int reg = warp; reg < R_; reg += 2) {
        const int ri = REG_RR[reg];
        const int c0 = REG_C0[reg];
        const int c1 = REG_C1[reg];
        float m = -FLT_MAX;
        for (int cc = c0 + lane; cc < c1; cc += 32)
            m = fmaxf(m, rr[ri][cc]);
        #pragma unroll
        for (int o = 16; o > 0; o >>= 1)
            m = fmaxf(m, __shfl_xor_sync(0xffffffffu, m, o));
        if (lane == 0)
            vecs[((size_t)(b * R_ + reg)) * C_ + c] = m;
    }
}

// ---------------------------------------------------------------------------
// Kernel 2: per-(b,r) inverse L2 norm. grid = 336 blocks x 256 threads.
// 2048 floats per block = 2 float4 per thread, from L2-resident vecs.
// ---------------------------------------------------------------------------
__global__ __launch_bounds__(256) void rpool_inv_kernel(
    const float* __restrict__ vecs, float* __restrict__ inv)
{
    const int br = blockIdx.x;                  // b * R + r
    const int tid = threadIdx.x;
    const float4* __restrict__ v4 =
        reinterpret_cast<const float4*>(vecs + (size_t)br * C_);

    const float4 a = v4[tid];
    const float4 b = v4[tid + 256];
    float acc = a.x * a.x + a.y * a.y + a.z * a.z + a.w * a.w
              + b.x * b.x + b.y * b.y + b.z * b.z + b.w * b.w;

    #pragma unroll
    for (int o = 16; o > 0; o >>= 1)
        acc += __shfl_xor_sync(0xffffffffu, acc, o);

    __shared__ float ws[8];
    const int lane = tid & 31, warp = tid >> 5;
    if (lane == 0) ws[warp] = acc;
    __syncthreads();
    if (warp == 0) {
        float t = (lane < 8) ? ws[lane] : 0.f;
        #pragma unroll
        for (int o = 4; o > 0; o >>= 1)
            t += __shfl_xor_sync(0xffffffffu, t, o);
        if (lane == 0) inv[br] = 1.0f / (sqrtf(t) + EPS_);
    }
}

// ---------------------------------------------------------------------------
// Kernel 3: aggregate. grid = 16 blocks x 512 threads; thread owns one float4
// of channels -> 21 independent L2 loads in flight (MLP=21), weighted sum,
// block-wide sum-of-squares, scaled store.
// ---------------------------------------------------------------------------
__global__ __launch_bounds__(512) void rpool_agg_kernel(
    const float* __restrict__ vecs, const float* __restrict__ inv,
    float* __restrict__ out)
{
    const int b = blockIdx.x;
    const int tid = threadIdx.x;                // 0..511 -> float4 index
    const int lane = tid & 31, warp = tid >> 5;
    const float4* __restrict__ vb4 =
        reinterpret_cast<const float4*>(vecs + (size_t)b * R_ * C_);

    __shared__ float w[R_];
    if (tid < R_) w[tid] = inv[b * R_ + tid];
    __syncthreads();

    float4 s = make_float4(0.f, 0.f, 0.f, 0.f);
    #pragma unroll
    for (int r = 0; r < R_; r++) {
        const float4 v = vb4[r * 512 + tid];
        const float k = w[r];
        s.x += v.x * k; s.y += v.y * k;
        s.z += v.z * k; s.w += v.w * k;
    }
    float local = s.x * s.x + s.y * s.y + s.z * s.z + s.w * s.w;

    #pragma unroll
    for (int o = 16; o > 0; o >>= 1)
        local += __shfl_xor_sync(0xffffffffu, local, o);
    __shared__ float ws[16];
    if (lane == 0) ws[warp] = local;
    __syncthreads();
    __shared__ float s_invn;
    if (warp == 0) {
        float t = (lane < 16) ? ws[lane] : 0.f;
        #pragma unroll
        for (int o = 8; o > 0; o >>= 1)
            t += __shfl_xor_sync(0xffffffffu, t, o);
        if (lane == 0) s_invn = 1.0f / (sqrtf(t) + EPS_);
    }
    __syncthreads();

    const float invn = s_invn;
    s.x *= invn; s.y *= invn; s.z *= invn; s.w *= invn;
    reinterpret_cast<float4*>(out)[(size_t)b * 512 + tid] = s;
}

extern "C" void kernel_launch(void* const* d_in, const int* in_sizes, int n_in,
                              void* d_out, int out_size)
{
    const float* x = (const float*)d_in[0];
    float* out = (float*)d_out;

    float* vecs;
    float* inv;
    cudaGetSymbolAddress((void**)&vecs, g_vecs);
    cudaGetSymbolAddress((void**)&inv, g_inv);

    rpool_max_kernel<<<NPLANE, 64>>>(x, vecs);
    rpool_inv_kernel<<<B_ * R_, 256>>>(vecs, inv);
    rpool_agg_kernel<<<B_, 512>>>(vecs, inv, out);
}

// round 5
// speedup vs baseline: 1.1630x; 1.0082x over previous
#include <cuda_runtime.h>
#include <float.h>
#include <math.h>

// x = [B=16, C=2048, H=48, W=64] fp32. 21 regions; 6 row ranges from 6 row
// segments (breakpoints 0,12,16,24,32,36,48).
#define B_  16
#define C_  2048
#define H_  48
#define W_  64
#define NPLANE (B_ * C_)
#define R_  21
#define EPS_ 1e-6f

__device__ float g_vecs[B_ * R_ * C_];    // [b][r][c]
__device__ float g_inv[B_ * R_];          // 1/(||v||+eps) per (b,r)

// RR0=[0,48) RR1=[0,32) RR2=[16,48) RR3=[0,24) RR4=[12,36) RR5=[24,48)
__constant__ int REG_RR[R_] = {
    0,
    0, 0,
    1, 1, 1,
    2, 2, 2,
    3, 3, 3, 3,
    4, 4, 4, 4,
    5, 5, 5, 5
};
__constant__ int REG_C0[R_] = {
    0,
    0, 16,
    0, 16, 32,
    0, 16, 32,
    0, 13, 26, 40,
    0, 13, 26, 40,
    0, 13, 26, 40
};
__constant__ int REG_C1[R_] = {
    64,
    48, 64,
    32, 48, 64,
    32, 48, 64,
    24, 37, 50, 64,
    24, 37, 50, 64,
    24, 37, 50, 64
};

// ---------------------------------------------------------------------------
// Kernel 1: one block per (b,c) plane, 64 threads = one per column.
// ALL 48 column loads are front-batched into registers (MLP ~48, just under
// the per-warp M_max of ~55 outstanding LDGs), THEN the segment max tree runs.
// Scalar LDG.32: one 128B L1tex wavefront per warp access (cross-LDG rate 1.0).
// ---------------------------------------------------------------------------
__global__ __launch_bounds__(64) void rpool_max_kernel(
    const float* __restrict__ x, float* __restrict__ vecs)
{
    const int plane = blockIdx.x;             // b * C + c
    const float* __restrict__ p = x + (size_t)plane * (H_ * W_) + threadIdx.x;
    const int col = threadIdx.x;              // 0..63

    // Front-batch: 48 independent loads, immediate offsets from one base.
    float v[48];
    #pragma unroll
    for (int r = 0; r < 48; r++)
        v[r] = p[r * W_];

    // Segment max tree (all inputs already in flight / landed).
    float s0 = v[0], s1 = v[12], s2 = v[16], s3 = v[24], s4 = v[32], s5 = v[36];
    #pragma unroll
    for (int r = 1; r < 12; r++)  s0 = fmaxf(s0, v[r]);
    #pragma unroll
    for (int r = 13; r < 16; r++) s1 = fmaxf(s1, v[r]);
    #pragma unroll
    for (int r = 17; r < 24; r++) s2 = fmaxf(s2, v[r]);
    #pragma unroll
    for (int r = 25; r < 32; r++) s3 = fmaxf(s3, v[r]);
    #pragma unroll
    for (int r = 33; r < 36; r++) s4 = fmaxf(s4, v[r]);
    #pragma unroll
    for (int r = 37; r < 48; r++) s5 = fmaxf(s5, v[r]);

    __shared__ float rr[6][W_];
    const float m012 = fmaxf(fmaxf(s0, s1), s2);
    const float m345 = fmaxf(fmaxf(s3, s4), s5);
    rr[0][col] = fmaxf(m012, m345);                     // rows [0,48)
    rr[1][col] = fmaxf(m012, s3);                       // rows [0,32)
    rr[2][col] = fmaxf(fmaxf(s2, s3), fmaxf(s4, s5));   // rows [16,48)
    rr[3][col] = m012;                                  // rows [0,24)
    rr[4][col] = fmaxf(fmaxf(s1, s2), fmaxf(s3, s4));   // rows [12,36)
    rr[5][col] = m345;                                  // rows [24,48)
    __syncthreads();

    const int warp = threadIdx.x >> 5;
    const int lane = threadIdx.x & 31;
    const int b = plane >> 11;          // / C_
    const int c = plane & (C_ - 1);     // % C_

    for (int reg = warp; reg < R_; reg += 2) {
        const int ri = REG_RR[reg];
        const int c0 = REG_C0[reg];
        const int c1 = REG_C1[reg];
        float m = -FLT_MAX;
        for (int cc = c0 + lane; cc < c1; cc += 32)
            m = fmaxf(m, rr[ri][cc]);
        #pragma unroll
        for (int o = 16; o > 0; o >>= 1)
            m = fmaxf(m, __shfl_xor_sync(0xffffffffu, m, o));
        if (lane == 0)
            vecs[((size_t)(b * R_ + reg)) * C_ + c] = m;
    }
}

// ---------------------------------------------------------------------------
// Kernel 2: per-(b,r) inverse L2 norm. grid = 336 blocks x 256 threads.
// ---------------------------------------------------------------------------
__global__ __launch_bounds__(256) void rpool_inv_kernel(
    const float* __restrict__ vecs, float* __restrict__ inv)
{
    const int br = blockIdx.x;                  // b * R + r
    const int tid = threadIdx.x;
    const float4* __restrict__ v4 =
        reinterpret_cast<const float4*>(vecs + (size_t)br * C_);

    const float4 a = v4[tid];
    const float4 b = v4[tid + 256];
    float acc = a.x * a.x + a.y * a.y + a.z * a.z + a.w * a.w
              + b.x * b.x + b.y * b.y + b.z * b.z + b.w * b.w;

    #pragma unroll
    for (int o = 16; o > 0; o >>= 1)
        acc += __shfl_xor_sync(0xffffffffu, acc, o);

    __shared__ float ws[8];
    const int lane = tid & 31, warp = tid >> 5;
    if (lane == 0) ws[warp] = acc;
    __syncthreads();
    if (warp == 0) {
        float t = (lane < 8) ? ws[lane] : 0.f;
        #pragma unroll
        for (int o = 4; o > 0; o >>= 1)
            t += __shfl_xor_sync(0xffffffffu, t, o);
        if (lane == 0) inv[br] = 1.0f / (sqrtf(t) + EPS_);
    }
}

// ---------------------------------------------------------------------------
// Kernel 3: aggregate. grid = 16 blocks x 512 threads.
// ---------------------------------------------------------------------------
__global__ __launch_bounds__(512) void rpool_agg_kernel(
    const float* __restrict__ vecs, const float* __restrict__ inv,
    float* __restrict__ out)
{
    const int b = blockIdx.x;
    const int tid = threadIdx.x;                // 0..511 -> float4 index
    const int lane = tid & 31, warp = tid >> 5;
    const float4* __restrict__ vb4 =
        reinterpret_cast<const float4*>(vecs + (size_t)b * R_ * C_);

    __shared__ float w[R_];
    if (tid < R_) w[tid] = inv[b * R_ + tid];
    __syncthreads();

    float4 s = make_float4(0.f, 0.f, 0.f, 0.f);
    #pragma unroll
    for (int r = 0; r < R_; r++) {
        const float4 v = vb4[r * 512 + tid];
        const float k = w[r];
        s.x += v.x * k; s.y += v.y * k;
        s.z += v.z * k; s.w += v.w * k;
    }
    float local = s.x * s.x + s.y * s.y + s.z * s.z + s.w * s.w;

    #pragma unroll
    for (int o = 16; o > 0; o >>= 1)
        local += __shfl_xor_sync(0xffffffffu, local, o);
    __shared__ float ws[16];
    if (lane == 0) ws[warp] = local;
    __syncthreads();
    __shared__ float s_invn;
    if (warp == 0) {
        float t = (lane < 16) ? ws[lane] : 0.f;
        #pragma unroll
        for (int o = 8; o > 0; o >>= 1)
            t += __shfl_xor_sync(0xffffffffu, t, o);
        if (lane == 0) s_invn = 1.0f / (sqrtf(t) + EPS_);
    }
    __syncthreads();

    const float invn = s_invn;
    s.x *= invn; s.y *= invn; s.z *= invn; s.w *= invn;
    reinterpret_cast<float4*>(out)[(size_t)b * 512 + tid] = s;
}

extern "C" void kernel_launch(void* const* d_in, const int* in_sizes, int n_in,
                              void* d_out, int out_size)
{
    const float* x = (const float*)d_in[0];
    float* out = (float*)d_out;

    float* vecs;
    float* inv;
    cudaGetSymbolAddress((void**)&vecs, g_vecs);
    cudaGetSymbolAddress((void**)&inv, g_inv);

    rpool_max_kernel<<<NPLANE, 64>>>(x, vecs);
    rpool_inv_kernel<<<B_ * R_, 256>>>(vecs, inv);
    rpool_agg_kernel<<<B_, 512>>>(vecs, inv, out);
}